// round 9
// baseline (speedup 1.0000x reference)
#include <cuda_runtime.h>
#include <math.h>

// ---------------- problem constants ----------------
#define BB       2
#define SEQ      2048
#define DMODEL   1024
#define DCONV    4
#define HEADDIM  64
#define CHUNKL   256
#define DINNER   2048
#define NHEADS   32
#define CONVDIM  2304   // DINNER + 2*DSTATE
#define DINPROJ  4384   // 2*DINNER + 2*DSTATE + NHEADS
#define DSTATE   128
#define DFF      4096
#define NC       8      // SEQ / CHUNKL
#define NROWS    (BB*SEQ)   // 4096

// ---------------- scratch (device globals; no runtime alloc) ----------------
__device__ float g_zx[(size_t)NROWS*DINPROJ];
__device__ float g_xbc[(size_t)NROWS*CONVDIM];
__device__ float g_xdt[(size_t)NROWS*DINNER];
__device__ float g_dt[(size_t)NROWS*NHEADS];
__device__ float g_draw[(size_t)NROWS*NHEADS];
__device__ float g_acum[(size_t)BB*NHEADS*SEQ];
__device__ float g_G[(size_t)BB*NC*CHUNKL*CHUNKL];
__device__ float g_states[(size_t)BB*NC*NHEADS*HEADDIM*DSTATE];
__device__ float g_prev  [(size_t)BB*NC*NHEADS*HEADDIM*DSTATE];
__device__ float g_y[(size_t)NROWS*DINNER];
__device__ float g_hidden[(size_t)NROWS*DMODEL];
__device__ float g_h[(size_t)NROWS*DMODEL];
__device__ float g_ff[(size_t)NROWS*DFF];
__device__ float g_ff2[(size_t)NROWS*DMODEL];

// ---------------- helpers ----------------
__device__ __forceinline__ float softplusf(float x) {
    return (x > 20.f) ? x : log1pf(expf(x));
}
__device__ __forceinline__ float siluf(float x) {
    return x / (1.f + expf(-x));
}
__device__ __forceinline__ float tf32r(float x) {
    unsigned r;
    asm("cvt.rna.tf32.f32 %0, %1;" : "=r"(r) : "f"(x));
    return __uint_as_float(r);
}
__device__ __forceinline__ unsigned tf32u(float x) {
    unsigned r;
    asm("cvt.rna.tf32.f32 %0, %1;" : "=r"(r) : "f"(x));
    return r;
}
__device__ __forceinline__ unsigned smem_u32(const void* p) {
    unsigned a;
    asm("{ .reg .u64 t; cvta.to.shared.u64 t, %1; cvt.u32.u64 %0, t; }" : "=r"(a) : "l"(p));
    return a;
}
__device__ __forceinline__ void mma_tf32(float* c, const unsigned* a, const unsigned* b) {
    asm volatile("mma.sync.aligned.m16n8k8.row.col.f32.tf32.tf32.f32 "
                 "{%0,%1,%2,%3}, {%4,%5,%6,%7}, {%8,%9}, {%0,%1,%2,%3};"
                 : "+f"(c[0]), "+f"(c[1]), "+f"(c[2]), "+f"(c[3])
                 : "r"(a[0]), "r"(a[1]), "r"(a[2]), "r"(a[3]),
                   "r"(b[0]), "r"(b[1]));
}

// ---------------- cp.async pipelined TF32 GEMM: C = act(A@B+bias) -----------
// CTA tile 256(M) x 128(N), warp tile 64x64. A: MxK row-major, B: KxN row-major.
// M%256==0, K%16==0 (>=64), N arbitrary (%4==0).
#define GSTAGES 4
#define ASTR    20                       // A smem stride (floats): conflict-free
#define BSTR    136                      // B smem stride (floats)
#define A_STF   (256*ASTR)               // 5120 floats per A stage
#define B_STF   (16*BSTR)                // 2176 floats per B stage
#define ST_F    (A_STF + B_STF)          // 7296
#define GT_SMEM (GSTAGES*ST_F*4)         // 116736 bytes

#define GT_ISSUE(stg, kt) do {                                                      \
    unsigned ab = smb + (unsigned)(stg) * (ST_F * 4);                               \
    unsigned bbs = ab + A_STF * 4;                                                  \
    int k0i = (kt) * 16;                                                            \
    _Pragma("unroll")                                                               \
    for (int u = 0; u < 4; u++) {                                                   \
        int c = tid * 4 + u;                                                        \
        int m = c >> 2, kq = (c & 3) << 2;                                          \
        const float* sp = A + (size_t)(row0 + m) * K + k0i + kq;                    \
        asm volatile("cp.async.cg.shared.global [%0], [%1], 16;"                    \
                     :: "r"(ab + (unsigned)(m * ASTR + kq) * 4), "l"(sp));          \
    }                                                                               \
    _Pragma("unroll")                                                               \
    for (int u = 0; u < 2; u++) {                                                   \
        int c = tid * 2 + u;                                                        \
        int kk = c >> 5, nq = (c & 31) << 2;                                        \
        int gc = col0 + nq;                                                         \
        const float* sp2 = (gc < N) ? (B + (size_t)(k0i + kk) * N + gc) : B;        \
        int by = (gc < N) ? 16 : 0;                                                 \
        asm volatile("cp.async.cg.shared.global [%0], [%1], 16, %2;"                \
                     :: "r"(bbs + (unsigned)(kk * BSTR + nq) * 4), "l"(sp2), "r"(by)); \
    }                                                                               \
    asm volatile("cp.async.commit_group;" ::: "memory");                            \
} while (0)

__global__ __launch_bounds__(256)
void gemm_tc(const float* __restrict__ A, const float* __restrict__ B,
             const float* __restrict__ bias, float* __restrict__ C,
             int M, int N, int K, int act)
{
    extern __shared__ float sm[];
    unsigned smb = smem_u32(sm);
    int tid = threadIdx.x;
    int lane = tid & 31, wid = tid >> 5;
    int wm = (wid >> 1) * 64;            // 4 warps along M (256)
    int wn = (wid & 1) * 64;             // 2 warps along N (128)
    int g = lane >> 2, tig = lane & 3;
    int row0 = blockIdx.y * 256, col0 = blockIdx.x * 128;

    float acc[4][8][4];
#pragma unroll
    for (int i = 0; i < 4; i++)
#pragma unroll
        for (int j = 0; j < 8; j++)
#pragma unroll
            for (int v = 0; v < 4; v++) acc[i][j][v] = 0.f;

    int nt = K / 16;           // >= 64 for all call sites
    GT_ISSUE(0, 0);
    GT_ISSUE(1, 1);
    GT_ISSUE(2, 2);

    for (int t = 0; t < nt; t++) {
        if (t + 3 <= nt)      asm volatile("cp.async.wait_group 2;" ::: "memory");
        else if (t + 2 == nt) asm volatile("cp.async.wait_group 1;" ::: "memory");
        else                  asm volatile("cp.async.wait_group 0;" ::: "memory");
        __syncthreads();
        if (t + 3 < nt) { GT_ISSUE((t + 3) & 3, t + 3); }

        const float* Ab = sm + (t & 3) * ST_F;
        const float* Bb = Ab + A_STF;
#pragma unroll
        for (int ks = 0; ks < 2; ks++) {
            int kb = ks * 8;
            unsigned af[4][4], bf[8][2];
#pragma unroll
            for (int mt = 0; mt < 4; mt++) {
                int m = wm + mt * 16;
                af[mt][0] = tf32u(Ab[(m + g) * ASTR + kb + tig]);
                af[mt][1] = tf32u(Ab[(m + g + 8) * ASTR + kb + tig]);
                af[mt][2] = tf32u(Ab[(m + g) * ASTR + kb + tig + 4]);
                af[mt][3] = tf32u(Ab[(m + g + 8) * ASTR + kb + tig + 4]);
            }
#pragma unroll
            for (int nt2 = 0; nt2 < 8; nt2++) {
                int n = wn + nt2 * 8;
                bf[nt2][0] = tf32u(Bb[(kb + tig) * BSTR + n + g]);
                bf[nt2][1] = tf32u(Bb[(kb + tig + 4) * BSTR + n + g]);
            }
#pragma unroll
            for (int mt = 0; mt < 4; mt++)
#pragma unroll
                for (int nt2 = 0; nt2 < 8; nt2++)
                    mma_tf32(acc[mt][nt2], af[mt], bf[nt2]);
        }
    }

    // epilogue
#pragma unroll
    for (int mt = 0; mt < 4; mt++) {
        int r = row0 + wm + mt * 16 + g;
#pragma unroll
        for (int nt2 = 0; nt2 < 8; nt2++) {
            int col = col0 + wn + nt2 * 8 + 2 * tig;
            if (col < N) {
                float b0 = bias[col], b1 = bias[col + 1];
                float v0 = acc[mt][nt2][0] + b0;
                float v1 = acc[mt][nt2][1] + b1;
                float v2 = acc[mt][nt2][2] + b0;
                float v3 = acc[mt][nt2][3] + b1;
                if (act == 1) {
                    float t;
                    t = fminf(fmaxf(v0 + 3.f, 0.f), 6.f); v0 = v0 * t * (1.f / 6.f);
                    t = fminf(fmaxf(v1 + 3.f, 0.f), 6.f); v1 = v1 * t * (1.f / 6.f);
                    t = fminf(fmaxf(v2 + 3.f, 0.f), 6.f); v2 = v2 * t * (1.f / 6.f);
                    t = fminf(fmaxf(v3 + 3.f, 0.f), 6.f); v3 = v3 * t * (1.f / 6.f);
                }
                C[(size_t)r * N + col] = v0;
                C[(size_t)r * N + col + 1] = v1;
                C[(size_t)(r + 8) * N + col] = v2;
                C[(size_t)(r + 8) * N + col + 1] = v3;
            }
        }
    }
}

// ---------------- exact fp32 dt_raw ----------------
__global__ void dtraw_kernel(const float* __restrict__ x, const float* __restrict__ W_in,
                             const float* __restrict__ b_in)
{
    int row0 = blockIdx.x * 8;
    int tid = threadIdx.x;
    int r = tid >> 5, h = tid & 31;
    __shared__ float xs[8][DMODEL];
    for (int i = tid; i < 8 * DMODEL; i += 256)
        xs[i >> 10][i & 1023] = x[(size_t)(row0 + (i >> 10)) * DMODEL + (i & 1023)];
    __syncthreads();
    const float* wc = W_in + (DINPROJ - NHEADS) + h;
    float a0 = 0.f, a1 = 0.f, a2 = 0.f, a3 = 0.f;
#pragma unroll 2
    for (int k = 0; k < DMODEL; k += 4) {
        a0 = fmaf(xs[r][k + 0], wc[(size_t)(k + 0) * DINPROJ], a0);
        a1 = fmaf(xs[r][k + 1], wc[(size_t)(k + 1) * DINPROJ], a1);
        a2 = fmaf(xs[r][k + 2], wc[(size_t)(k + 2) * DINPROJ], a2);
        a3 = fmaf(xs[r][k + 3], wc[(size_t)(k + 3) * DINPROJ], a3);
    }
    g_draw[(size_t)(row0 + r) * NHEADS + h] =
        b_in[DINPROJ - NHEADS + h] + ((a0 + a1) + (a2 + a3));
}

// ---------------- conv + silu + fused xdt (4 seq positions / thread) --------
__global__ void conv_kernel(const float* __restrict__ conv_w, const float* __restrict__ conv_b)
{
    int idx = blockIdx.x * blockDim.x + threadIdx.x;
    if (idx >= (NROWS / 4) * CONVDIM) return;
    int ch = idx % CONVDIM;
    int rg = idx / CONVDIM;
    int row0 = rg * 4;
    int l0 = row0 % SEQ;
    float w0 = conv_w[ch * DCONV + 0], w1 = conv_w[ch * DCONV + 1];
    float w2 = conv_w[ch * DCONV + 2], w3 = conv_w[ch * DCONV + 3];
    float bv = conv_b[ch];
    float v[7];
#pragma unroll
    for (int j = 0; j < 7; j++) {
        int l = l0 + j - 3;
        v[j] = (l >= 0) ? g_zx[(size_t)(row0 + j - 3) * DINPROJ + DINNER + ch] : 0.f;
    }
#pragma unroll
    for (int i = 0; i < 4; i++) {
        float a = bv;
        a = fmaf(v[i], w0, a);
        a = fmaf(v[i + 1], w1, a);
        a = fmaf(v[i + 2], w2, a);
        a = fmaf(v[i + 3], w3, a);
        float o = siluf(a);
        size_t row = row0 + i;
        g_xbc[row * CONVDIM + ch] = o;
        if (ch < DINNER)
            g_xdt[row * DINNER + ch] = o * g_dt[row * NHEADS + (ch >> 6)];
    }
}

// ---------------- dt / dA + per-chunk inclusive cumsum (exact exp) ----------
__global__ void dtscan_kernel(const float* __restrict__ tdiff,
                              const float* __restrict__ A_log,
                              const float* __restrict__ dt_bias,
                              const float* __restrict__ time_decay)
{
    int blk = blockIdx.x;
    int c = blk % NC;
    int h = (blk / NC) % NHEADS;
    int b = blk / (NC * NHEADS);
    int l = threadIdx.x;
    __shared__ float s[CHUNKL];
    int row = b * SEQ + c * CHUNKL + l;
    float draw = g_draw[(size_t)row * NHEADS + h];
    float dt = softplusf(draw + dt_bias[h]);
    float Ah = -expf(A_log[h]);
    float spd = softplusf(time_decay[h]);
    float dA = dt * Ah - spd * tdiff[row];
    g_dt[(size_t)row * NHEADS + h] = dt;
    s[l] = dA;
    __syncthreads();
    for (int off = 1; off < CHUNKL; off <<= 1) {
        float v = (l >= off) ? s[l - off] : 0.f;
        __syncthreads();
        s[l] += v;
        __syncthreads();
    }
    g_acum[((size_t)(b * NHEADS + h)) * SEQ + c * CHUNKL + l] = s[l];
}

// ---------------- G = C @ B^T per (b,chunk)  [tf32 mma, 64x64 tiles] --------
__global__ __launch_bounds__(256)
void cbgemm_kernel()
{
    int bc = blockIdx.z;
    int l0 = blockIdx.y * 64, s0 = blockIdx.x * 64;
    __shared__ float As[16][72];
    __shared__ float Bs2[16][72];
    int tid = threadIdx.x;
    int lane = tid & 31, wid = tid >> 5;
    int wm = (wid & 3) * 16;
    int wn = (wid >> 2) * 32;
    int g = lane >> 2, tig = lane & 3;

    float acc[4][4];
#pragma unroll
    for (int j = 0; j < 4; j++)
#pragma unroll
        for (int v = 0; v < 4; v++) acc[j][v] = 0.f;

    const float* base = g_xbc + (size_t)bc * CHUNKL * CONVDIM;
    int r = tid >> 2, c4 = (tid & 3) << 2;
    for (int n0 = 0; n0 < DSTATE; n0 += 16) {
        float4 vc = *(const float4*)(base + (size_t)(l0 + r) * CONVDIM + DINNER + DSTATE + n0 + c4);
        As[c4 + 0][r] = tf32r(vc.x); As[c4 + 1][r] = tf32r(vc.y);
        As[c4 + 2][r] = tf32r(vc.z); As[c4 + 3][r] = tf32r(vc.w);
        float4 vb = *(const float4*)(base + (size_t)(s0 + r) * CONVDIM + DINNER + n0 + c4);
        Bs2[c4 + 0][r] = tf32r(vb.x); Bs2[c4 + 1][r] = tf32r(vb.y);
        Bs2[c4 + 2][r] = tf32r(vb.z); Bs2[c4 + 3][r] = tf32r(vb.w);
        __syncthreads();
#pragma unroll
        for (int ks = 0; ks < 2; ks++) {
            int kb = ks * 8;
            unsigned af[4], bf[4][2];
            af[0] = __float_as_uint(As[kb + tig][wm + g]);
            af[1] = __float_as_uint(As[kb + tig][wm + g + 8]);
            af[2] = __float_as_uint(As[kb + tig + 4][wm + g]);
            af[3] = __float_as_uint(As[kb + tig + 4][wm + g + 8]);
#pragma unroll
            for (int nt = 0; nt < 4; nt++) {
                int n = wn + nt * 8;
                bf[nt][0] = __float_as_uint(Bs2[kb + tig][n + g]);
                bf[nt][1] = __float_as_uint(Bs2[kb + tig + 4][n + g]);
            }
#pragma unroll
            for (int nt = 0; nt < 4; nt++)
                mma_tf32(acc[nt], af, bf[nt]);
        }
        __syncthreads();
    }
    float* Gp = g_G + (size_t)bc * CHUNKL * CHUNKL;
    int rr = l0 + wm + g;
#pragma unroll
    for (int nt = 0; nt < 4; nt++) {
        int col = s0 + wn + nt * 8 + 2 * tig;
        Gp[(size_t)rr * CHUNKL + col]     = acc[nt][0];
        Gp[(size_t)rr * CHUNKL + col + 1] = acc[nt][1];
        Gp[(size_t)(rr + 8) * CHUNKL + col]     = acc[nt][2];
        Gp[(size_t)(rr + 8) * CHUNKL + col + 1] = acc[nt][3];
    }
}

// ---------------- chunk states  [tf32 mma, __expf] ----------------
__global__ __launch_bounds__(256)
void states_kernel()
{
    int bch = blockIdx.x;
    int h = bch % NHEADS;
    int bc = bch / NHEADS;
    int b = bc / NC, c = bc % NC;
    int tid = threadIdx.x;
    int lane = tid & 31, wid = tid >> 5;
    int wm = (wid >> 1) * 16;
    int wn = (wid & 1) * 64;
    int g = lane >> 2, tig = lane & 3;

    __shared__ float w[CHUNKL];
    __shared__ float As[16][72];
    __shared__ float Bs[16][136];
    const float* ac = g_acum + ((size_t)(b * NHEADS + h)) * SEQ + c * CHUNKL;
    w[tid] = __expf(ac[CHUNKL - 1] - ac[tid]);
    __syncthreads();

    float acc[8][4];
#pragma unroll
    for (int j = 0; j < 8; j++)
#pragma unroll
        for (int v = 0; v < 4; v++) acc[j][v] = 0.f;

    for (int l0 = 0; l0 < CHUNKL; l0 += 16) {
        {
            int lr = tid >> 4, pc = (tid & 15) << 2;
            float4 v = *(const float4*)(g_xdt + ((size_t)(bc * CHUNKL + l0 + lr)) * DINNER + h * HEADDIM + pc);
            float ww = w[l0 + lr];
            As[lr][pc + 0] = tf32r(v.x * ww); As[lr][pc + 1] = tf32r(v.y * ww);
            As[lr][pc + 2] = tf32r(v.z * ww); As[lr][pc + 3] = tf32r(v.w * ww);
        }
#pragma unroll
        for (int u = 0; u < 2; u++) {
            int id = tid * 2 + u;
            int lr2 = id >> 5, nc4 = (id & 31) << 2;
            float4 vb = *(const float4*)(g_xbc + ((size_t)(bc * CHUNKL + l0 + lr2)) * CONVDIM + DINNER + nc4);
            Bs[lr2][nc4 + 0] = tf32r(vb.x); Bs[lr2][nc4 + 1] = tf32r(vb.y);
            Bs[lr2][nc4 + 2] = tf32r(vb.z); Bs[lr2][nc4 + 3] = tf32r(vb.w);
        }
        __syncthreads();
#pragma unroll
        for (int ks = 0; ks < 2; ks++) {
            int kb = ks * 8;
            unsigned af[4], bf[8][2];
            af[0] = __float_as_uint(As[kb + tig][wm + g]);
            af[1] = __float_as_uint(As[kb + tig][wm + g + 8]);
            af[2] = __float_as_uint(As[kb + tig + 4][wm + g]);
            af[3] = __float_as_uint(As[kb + tig + 4][wm + g + 8]);
#pragma unroll
            for (int nt = 0; nt < 8; nt++) {
                int n = wn + nt * 8;
                bf[nt][0] = __float_as_uint(Bs[kb + tig][n + g]);
                bf[nt][1] = __float_as_uint(Bs[kb + tig + 4][n + g]);
            }
#pragma unroll
            for (int nt = 0; nt < 8; nt++)
                mma_tf32(acc[nt], af, bf[nt]);
        }
        __syncthreads();
    }
    float* sp = g_states + (size_t)bch * HEADDIM * DSTATE;
    int r = wm + g;
#pragma unroll
    for (int nt = 0; nt < 8; nt++) {
        int col = wn + nt * 8 + 2 * tig;
        sp[(size_t)r * DSTATE + col]     = acc[nt][0];
        sp[(size_t)r * DSTATE + col + 1] = acc[nt][1];
        sp[(size_t)(r + 8) * DSTATE + col]     = acc[nt][2];
        sp[(size_t)(r + 8) * DSTATE + col + 1] = acc[nt][3];
    }
}

// ---------------- inter-chunk scan  [__expf] ----------------
__global__ void scan_kernel()
{
    int idx = blockIdx.x * blockDim.x + threadIdx.x;
    if (idx >= BB * NHEADS * HEADDIM * DSTATE) return;
    int n = idx & 127;
    int p = (idx >> 7) & 63;
    int h = (idx >> 13) & 31;
    int b = idx >> 18;
    float carry = 0.f;
    for (int c = 0; c < NC; c++) {
        size_t off = ((size_t)((b * NC + c) * NHEADS + h)) * (HEADDIM * DSTATE) + p * DSTATE + n;
        g_prev[off] = carry;
        float cd = __expf(g_acum[((size_t)(b * NHEADS + h)) * SEQ + c * CHUNKL + CHUNKL - 1]);
        carry = carry * cd + g_states[off];
    }
}

// ---------------- Y = (Y_diag + Y_off + D*xh) * silu(z)  [tf32 mma, __expf] -
__global__ __launch_bounds__(256)
void ydiag_kernel(const float* __restrict__ Dp)
{
    int bch = blockIdx.x;
    int h = bch % NHEADS;
    int bc = bch / NHEADS;
    int b = bc / NC;
    int tid = threadIdx.x;
    int lane = tid & 31, wid = tid >> 5;
    int g = lane >> 2, tig = lane & 3;
    int wm = wid * 32;

    __shared__ float Acs[CHUNKL];
    __shared__ float Gs[16][260];
    __shared__ float Xs[16][68];

    const float* ac = g_acum + ((size_t)(b * NHEADS + h)) * SEQ + (bc % NC) * CHUNKL;
    Acs[tid] = ac[tid];
    __syncthreads();
    float al = Acs[tid];
    float eal = __expf(al);

    float acc[2][8][4];
#pragma unroll
    for (int i = 0; i < 2; i++)
#pragma unroll
        for (int j = 0; j < 8; j++)
#pragma unroll
            for (int v = 0; v < 4; v++) acc[i][j][v] = 0.f;

    const float* Gp = g_G + (size_t)bc * CHUNKL * CHUNKL;

    for (int s0 = 0; s0 < CHUNKL; s0 += 16) {
        float4 gv[4];
#pragma unroll
        for (int q = 0; q < 4; q++)
            gv[q] = *(const float4*)(Gp + (size_t)tid * CHUNKL + s0 + q * 4);
        const float* gf = (const float*)gv;
#pragma unroll
        for (int i = 0; i < 16; i++) {
            int s = s0 + i;
            float v = 0.f;
            if (tid >= s) v = gf[i] * __expf(al - Acs[s]);
            Gs[i][tid] = tf32r(v);
        }
        {
            int lr = tid >> 4, pc = (tid & 15) << 2;
            float4 v4 = *(const float4*)(g_xdt + ((size_t)(bc * CHUNKL + s0 + lr)) * DINNER + h * HEADDIM + pc);
            Xs[lr][pc + 0] = tf32r(v4.x); Xs[lr][pc + 1] = tf32r(v4.y);
            Xs[lr][pc + 2] = tf32r(v4.z); Xs[lr][pc + 3] = tf32r(v4.w);
        }
        __syncthreads();
#pragma unroll
        for (int ks = 0; ks < 2; ks++) {
            int kb = ks * 8;
            unsigned af[2][4], bf[8][2];
#pragma unroll
            for (int mt = 0; mt < 2; mt++) {
                int m = wm + mt * 16;
                af[mt][0] = __float_as_uint(Gs[kb + tig][m + g]);
                af[mt][1] = __float_as_uint(Gs[kb + tig][m + g + 8]);
                af[mt][2] = __float_as_uint(Gs[kb + tig + 4][m + g]);
                af[mt][3] = __float_as_uint(Gs[kb + tig + 4][m + g + 8]);
            }
#pragma unroll
            for (int nt = 0; nt < 8; nt++) {
                int n = nt * 8;
                bf[nt][0] = __float_as_uint(Xs[kb + tig][n + g]);
                bf[nt][1] = __float_as_uint(Xs[kb + tig + 4][n + g]);
            }
#pragma unroll
            for (int mt = 0; mt < 2; mt++)
#pragma unroll
                for (int nt = 0; nt < 8; nt++)
                    mma_tf32(acc[mt][nt], af[mt], bf[nt]);
        }
        __syncthreads();
    }

    const float* pv_base = g_prev + (size_t)bch * HEADDIM * DSTATE;
    for (int n0 = 0; n0 < DSTATE; n0 += 16) {
        float4 cv[4];
#pragma unroll
        for (int q = 0; q < 4; q++)
            cv[q] = *(const float4*)(g_xbc + ((size_t)(bc * CHUNKL + tid)) * CONVDIM + DINNER + DSTATE + n0 + q * 4);
        const float* cf = (const float*)cv;
#pragma unroll
        for (int i = 0; i < 16; i++)
            Gs[i][tid] = tf32r(cf[i] * eal);
        {
            int p = tid >> 2, k4 = (tid & 3) << 2;
            float4 pvv = *(const float4*)(pv_base + (size_t)p * DSTATE + n0 + k4);
            Xs[k4 + 0][p] = tf32r(pvv.x); Xs[k4 + 1][p] = tf32r(pvv.y);
            Xs[k4 + 2][p] = tf32r(pvv.z); Xs[k4 + 3][p] = tf32r(pvv.w);
        }
        __syncthreads();
#pragma unroll
        for (int ks = 0; ks < 2; ks++) {
            int kb = ks * 8;
            unsigned af[2][4], bf[8][2];
#pragma unroll
            for (int mt = 0; mt < 2; mt++) {
                int m = wm + mt * 16;
                af[mt][0] = __float_as_uint(Gs[kb + tig][m + g]);
                af[mt][1] = __float_as_uint(Gs[kb + tig][m + g + 8]);
                af[mt][2] = __float_as_uint(Gs[kb + tig + 4][m + g]);
                af[mt][3] = __float_as_uint(Gs[kb + tig + 4][m + g + 8]);
            }
#pragma unroll
            for (int nt = 0; nt < 8; nt++) {
                int n = nt * 8;
                bf[nt][0] = __float_as_uint(Xs[kb + tig][n + g]);
                bf[nt][1] = __float_as_uint(Xs[kb + tig + 4][n + g]);
            }
#pragma unroll
            for (int mt = 0; mt < 2; mt++)
#pragma unroll
                for (int nt = 0; nt < 8; nt++)
                    mma_tf32(acc[mt][nt], af[mt], bf[nt]);
        }
        __syncthreads();
    }

    float Dh = Dp[h];
#pragma unroll
    for (int mt = 0; mt < 2; mt++) {
        int r0 = wm + mt * 16 + g;
#pragma unroll
        for (int nt = 0; nt < 8; nt++) {
            int pcol = nt * 8 + 2 * tig;
            int d = h * HEADDIM + pcol;
#pragma unroll
            for (int half = 0; half < 2; half++) {
                int l = r0 + half * 8;
                size_t row = (size_t)bc * CHUNKL + l;
                float xh0 = g_xbc[row * CONVDIM + d];
                float xh1 = g_xbc[row * CONVDIM + d + 1];
                float z0 = g_zx[row * DINPROJ + d];
                float z1 = g_zx[row * DINPROJ + d + 1];
                float v0 = acc[mt][nt][half * 2 + 0] + Dh * xh0;
                float v1 = acc[mt][nt][half * 2 + 1] + Dh * xh1;
                v0 *= siluf(z0);
                v1 *= siluf(z1);
                g_y[row * DINNER + d] = v0;
                g_y[row * DINNER + d + 1] = v1;
            }
        }
    }
}

// ---------------- gated RMS norm ----------------
__global__ void rms_kernel(const float* __restrict__ rms_w)
{
    int row = blockIdx.x;
    int tid = threadIdx.x;
    float* y = g_y + (size_t)row * DINNER;
    float ss = 0.f;
    for (int i = tid; i < DINNER; i += 256) { float v = y[i]; ss = fmaf(v, v, ss); }
    __shared__ float red[256];
    red[tid] = ss; __syncthreads();
    for (int o = 128; o > 0; o >>= 1) { if (tid < o) red[tid] += red[tid + o]; __syncthreads(); }
    float scale = rsqrtf(red[0] * (1.f / DINNER) + 1e-12f);
    for (int i = tid; i < DINNER; i += 256) y[i] = y[i] * scale * rms_w[i];
}

// ---------------- residual add + LayerNorm ----------------
__global__ void addln_kernel(const float* __restrict__ in1, const float* __restrict__ res,
                             const float* __restrict__ g, const float* __restrict__ bta,
                             float* __restrict__ out)
{
    int row = blockIdx.x;
    int tid = threadIdx.x;
    __shared__ float buf[DMODEL];
    __shared__ float red[256];
    float s = 0.f;
    for (int i = tid; i < DMODEL; i += 256) {
        float v = in1[(size_t)row * DMODEL + i] + res[(size_t)row * DMODEL + i];
        buf[i] = v; s += v;
    }
    red[tid] = s; __syncthreads();
    for (int o = 128; o > 0; o >>= 1) { if (tid < o) red[tid] += red[tid + o]; __syncthreads(); }
    float mu = red[0] * (1.f / DMODEL);
    __syncthreads();
    float vs = 0.f;
    for (int i = tid; i < DMODEL; i += 256) { float d = buf[i] - mu; vs = fmaf(d, d, vs); }
    red[tid] = vs; __syncthreads();
    for (int o = 128; o > 0; o >>= 1) { if (tid < o) red[tid] += red[tid + o]; __syncthreads(); }
    float inv = rsqrtf(red[0] * (1.f / DMODEL) + 1e-12f);
    for (int i = tid; i < DMODEL; i += 256)
        out[(size_t)row * DMODEL + i] = (buf[i] - mu) * inv * g[i] + bta[i];
}

// ---------------- launch ----------------
extern "C" void kernel_launch(void* const* d_in, const int* in_sizes, int n_in,
                              void* d_out, int out_size)
{
    const float* x          = (const float*)d_in[0];
    const float* time_diff  = (const float*)d_in[1];
    const float* W_in       = (const float*)d_in[2];
    const float* b_in       = (const float*)d_in[3];
    const float* conv_w     = (const float*)d_in[4];
    const float* conv_b     = (const float*)d_in[5];
    const float* A_log      = (const float*)d_in[6];
    const float* dt_bias    = (const float*)d_in[7];
    const float* Dp         = (const float*)d_in[8];
    const float* time_decay = (const float*)d_in[9];
    const float* rms_w      = (const float*)d_in[10];
    const float* W_out      = (const float*)d_in[11];
    const float* b_out      = (const float*)d_in[12];
    const float* ln_g       = (const float*)d_in[13];
    const float* ln_b       = (const float*)d_in[14];
    const float* fc1_w      = (const float*)d_in[15];
    const float* fc1_b      = (const float*)d_in[16];
    const float* fc2_w      = (const float*)d_in[17];
    const float* fc2_b      = (const float*)d_in[18];
    const float* ln2_g      = (const float*)d_in[19];
    const float* ln2_b      = (const float*)d_in[20];
    float* out = (float*)d_out;

    float *p_zx, *p_y, *p_hidden, *p_h, *p_ff, *p_ff2;
    cudaGetSymbolAddress((void**)&p_zx, g_zx);
    cudaGetSymbolAddress((void**)&p_y, g_y);
    cudaGetSymbolAddress((void**)&p_hidden, g_hidden);
    cudaGetSymbolAddress((void**)&p_h, g_h);
    cudaGetSymbolAddress((void**)&p_ff, g_ff);
    cudaGetSymbolAddress((void**)&p_ff2, g_ff2);

    cudaFuncSetAttribute(gemm_tc, cudaFuncAttributeMaxDynamicSharedMemorySize, GT_SMEM);

    // 1. in_proj  (CTA 256x128)
    gemm_tc<<<dim3((DINPROJ + 127) / 128, NROWS / 256), 256, GT_SMEM>>>(
        x, W_in, b_in, p_zx, NROWS, DINPROJ, DMODEL, 0);
    // 1b. exact fp32 dt_raw
    dtraw_kernel<<<NROWS / 8, 256>>>(x, W_in, b_in);
    // 2. dt / dA / chunk cumsum
    dtscan_kernel<<<BB * NHEADS * NC, CHUNKL>>>(time_diff, A_log, dt_bias, time_decay);
    // 3. conv + silu + fused xdt
    conv_kernel<<<((NROWS / 4) * CONVDIM + 255) / 256, 256>>>(conv_w, conv_b);
    // 4. G = C @ B^T  [tf32, 64x64]
    cbgemm_kernel<<<dim3(4, 4, BB * NC), 256>>>();
    // 5. chunk states [tf32, __expf]
    states_kernel<<<BB * NC * NHEADS, 256>>>();
    // 6. inter-chunk scan [__expf]
    scan_kernel<<<(BB * NHEADS * HEADDIM * DSTATE + 255) / 256, 256>>>();
    // 7. Y [tf32, __expf]
    ydiag_kernel<<<BB * NC * NHEADS, 256>>>(Dp);
    // 8. gated RMS norm
    rms_kernel<<<NROWS, 256>>>(rms_w);
    // 9. out_proj
    gemm_tc<<<dim3(DMODEL / 128, NROWS / 256), 256, GT_SMEM>>>(
        p_y, W_out, b_out, p_hidden, NROWS, DMODEL, DINNER, 0);
    // 10. h = LN(hidden + x)
    addln_kernel<<<NROWS, 256>>>(p_hidden, x, ln_g, ln_b, p_h);
    // 11. fc1 + hardswish
    gemm_tc<<<dim3(DFF / 128, NROWS / 256), 256, GT_SMEM>>>(
        p_h, fc1_w, fc1_b, p_ff, NROWS, DFF, DMODEL, 1);
    // 12. fc2
    gemm_tc<<<dim3(DMODEL / 128, NROWS / 256), 256, GT_SMEM>>>(
        p_ff, fc2_w, fc2_b, p_ff2, NROWS, DMODEL, DFF, 0);
    // 13. out = LN(ff2 + h)
    addln_kernel<<<NROWS, 256>>>(p_ff2, p_h, ln2_g, ln2_b, out);
    // 14. time_diff passthrough
    cudaMemcpyAsync(out + (size_t)NROWS * DMODEL, time_diff,
                    (size_t)BB * SEQ * sizeof(float), cudaMemcpyDeviceToDevice);
}

// round 10
// speedup vs baseline: 1.2540x; 1.2540x over previous
#include <cuda_runtime.h>
#include <math.h>

// ---------------- problem constants ----------------
#define BB       2
#define SEQ      2048
#define DMODEL   1024
#define DCONV    4
#define HEADDIM  64
#define CHUNKL   256
#define DINNER   2048
#define NHEADS   32
#define CONVDIM  2304   // DINNER + 2*DSTATE
#define DINPROJ  4384   // 2*DINNER + 2*DSTATE + NHEADS
#define DSTATE   128
#define DFF      4096
#define NC       8      // SEQ / CHUNKL
#define NROWS    (BB*SEQ)   // 4096

// ---------------- scratch (device globals; no runtime alloc) ----------------
__device__ float g_zx[(size_t)NROWS*DINPROJ];
__device__ float g_xbc[(size_t)NROWS*CONVDIM];
__device__ float g_xdt[(size_t)NROWS*DINNER];
__device__ float g_dt[(size_t)NROWS*NHEADS];
__device__ float g_draw[(size_t)NROWS*NHEADS];
__device__ float g_acum[(size_t)BB*NHEADS*SEQ];
__device__ float g_G[(size_t)BB*NC*CHUNKL*CHUNKL];
__device__ float g_states[(size_t)BB*NC*NHEADS*HEADDIM*DSTATE];
__device__ float g_prev  [(size_t)BB*NC*NHEADS*HEADDIM*DSTATE];
__device__ float g_y[(size_t)NROWS*DINNER];
__device__ float g_hidden[(size_t)NROWS*DMODEL];
__device__ float g_h[(size_t)NROWS*DMODEL];
__device__ float g_ff[(size_t)NROWS*DFF];
__device__ float g_ff2[(size_t)NROWS*DMODEL];

// ---------------- helpers ----------------
__device__ __forceinline__ float softplusf(float x) {
    return (x > 20.f) ? x : log1pf(expf(x));
}
__device__ __forceinline__ float siluf(float x) {
    return x / (1.f + expf(-x));
}
__device__ __forceinline__ float tf32r(float x) {
    unsigned r;
    asm("cvt.rna.tf32.f32 %0, %1;" : "=r"(r) : "f"(x));
    return __uint_as_float(r);
}
__device__ __forceinline__ unsigned tf32u(float x) {
    unsigned r;
    asm("cvt.rna.tf32.f32 %0, %1;" : "=r"(r) : "f"(x));
    return r;
}
__device__ __forceinline__ unsigned smem_u32(const void* p) {
    unsigned a;
    asm("{ .reg .u64 t; cvta.to.shared.u64 t, %1; cvt.u32.u64 %0, t; }" : "=r"(a) : "l"(p));
    return a;
}
__device__ __forceinline__ void mma_tf32(float* c, const unsigned* a, const unsigned* b) {
    asm volatile("mma.sync.aligned.m16n8k8.row.col.f32.tf32.tf32.f32 "
                 "{%0,%1,%2,%3}, {%4,%5,%6,%7}, {%8,%9}, {%0,%1,%2,%3};"
                 : "+f"(c[0]), "+f"(c[1]), "+f"(c[2]), "+f"(c[3])
                 : "r"(a[0]), "r"(a[1]), "r"(a[2]), "r"(a[3]),
                   "r"(b[0]), "r"(b[1]));
}

// ---------------- cp.async pipelined TF32 GEMM: C = act(A@B+bias) -----------
// CTA tile 128x128, warp tile 32x64, 3-stage pipeline, 2 CTAs/SM.
#define GSTAGES 3
#define ASTR    20                       // A smem stride (floats): conflict-free
#define BSTR    136                      // B smem stride (floats)
#define A_STF   (128*ASTR)               // 2560 floats per A stage
#define B_STF   (16*BSTR)                // 2176 floats per B stage
#define ST_F    (A_STF + B_STF)          // 4736
#define GT_SMEM (GSTAGES*ST_F*4)         // 56832 bytes

#define GT_ISSUE(stg, kt) do {                                                      \
    unsigned ab = smb + (unsigned)(stg) * (ST_F * 4);                               \
    unsigned bbs = ab + A_STF * 4;                                                  \
    int k0i = (kt) * 16;                                                            \
    _Pragma("unroll")                                                               \
    for (int u = 0; u < 2; u++) {                                                   \
        int c = tid * 2 + u;                                                        \
        int m = c >> 2, kq = (c & 3) << 2;                                          \
        const float* sp = A + (size_t)(row0 + m) * K + k0i + kq;                    \
        asm volatile("cp.async.cg.shared.global [%0], [%1], 16;"                    \
                     :: "r"(ab + (unsigned)(m * ASTR + kq) * 4), "l"(sp));          \
        int kk = c >> 5, nq = (c & 31) << 2;                                        \
        int gc = col0 + nq;                                                         \
        const float* sp2 = (gc < N) ? (B + (size_t)(k0i + kk) * N + gc) : B;        \
        int by = (gc < N) ? 16 : 0;                                                 \
        asm volatile("cp.async.cg.shared.global [%0], [%1], 16, %2;"                \
                     :: "r"(bbs + (unsigned)(kk * BSTR + nq) * 4), "l"(sp2), "r"(by)); \
    }                                                                               \
    asm volatile("cp.async.commit_group;" ::: "memory");                            \
} while (0)

__global__ __launch_bounds__(256, 2)
void gemm_tc(const float* __restrict__ A, const float* __restrict__ B,
             const float* __restrict__ bias, float* __restrict__ C,
             int M, int N, int K, int act)
{
    extern __shared__ float sm[];
    unsigned smb = smem_u32(sm);
    int tid = threadIdx.x;
    int lane = tid & 31, wid = tid >> 5;
    int wm = (wid >> 1) * 32;
    int wn = (wid & 1) * 64;
    int g = lane >> 2, tig = lane & 3;
    int row0 = blockIdx.y * 128, col0 = blockIdx.x * 128;

    float acc[2][8][4];
#pragma unroll
    for (int i = 0; i < 2; i++)
#pragma unroll
        for (int j = 0; j < 8; j++)
#pragma unroll
            for (int v = 0; v < 4; v++) acc[i][j][v] = 0.f;

    int nt = K / 16;           // >= 64 for all call sites
    GT_ISSUE(0, 0);
    GT_ISSUE(1, 1);

    int stg = 0;               // buffer holding tile t
    for (int t = 0; t < nt; t++) {
        if (t + 2 <= nt) asm volatile("cp.async.wait_group 1;" ::: "memory");
        else             asm volatile("cp.async.wait_group 0;" ::: "memory");
        __syncthreads();
        if (t + 2 < nt) {
            int nstg = stg + 2; if (nstg >= GSTAGES) nstg -= GSTAGES;
            GT_ISSUE(nstg, t + 2);
        }

        const float* Ab = sm + stg * ST_F;
        const float* Bb = Ab + A_STF;
#pragma unroll
        for (int ks = 0; ks < 2; ks++) {
            int kb = ks * 8;
            unsigned af[2][4], bf[8][2];
#pragma unroll
            for (int mt = 0; mt < 2; mt++) {
                int m = wm + mt * 16;
                af[mt][0] = tf32u(Ab[(m + g) * ASTR + kb + tig]);
                af[mt][1] = tf32u(Ab[(m + g + 8) * ASTR + kb + tig]);
                af[mt][2] = tf32u(Ab[(m + g) * ASTR + kb + tig + 4]);
                af[mt][3] = tf32u(Ab[(m + g + 8) * ASTR + kb + tig + 4]);
            }
#pragma unroll
            for (int nt2 = 0; nt2 < 8; nt2++) {
                int n = wn + nt2 * 8;
                bf[nt2][0] = tf32u(Bb[(kb + tig) * BSTR + n + g]);
                bf[nt2][1] = tf32u(Bb[(kb + tig + 4) * BSTR + n + g]);
            }
#pragma unroll
            for (int mt = 0; mt < 2; mt++)
#pragma unroll
                for (int nt2 = 0; nt2 < 8; nt2++)
                    mma_tf32(acc[mt][nt2], af[mt], bf[nt2]);
        }
        stg++; if (stg >= GSTAGES) stg = 0;
    }

    // epilogue
#pragma unroll
    for (int mt = 0; mt < 2; mt++) {
        int r = row0 + wm + mt * 16 + g;
#pragma unroll
        for (int nt2 = 0; nt2 < 8; nt2++) {
            int col = col0 + wn + nt2 * 8 + 2 * tig;
            if (col < N) {
                float b0 = bias[col], b1 = bias[col + 1];
                float v0 = acc[mt][nt2][0] + b0;
                float v1 = acc[mt][nt2][1] + b1;
                float v2 = acc[mt][nt2][2] + b0;
                float v3 = acc[mt][nt2][3] + b1;
                if (act == 1) {
                    float t;
                    t = fminf(fmaxf(v0 + 3.f, 0.f), 6.f); v0 = v0 * t * (1.f / 6.f);
                    t = fminf(fmaxf(v1 + 3.f, 0.f), 6.f); v1 = v1 * t * (1.f / 6.f);
                    t = fminf(fmaxf(v2 + 3.f, 0.f), 6.f); v2 = v2 * t * (1.f / 6.f);
                    t = fminf(fmaxf(v3 + 3.f, 0.f), 6.f); v3 = v3 * t * (1.f / 6.f);
                }
                C[(size_t)r * N + col] = v0;
                C[(size_t)r * N + col + 1] = v1;
                C[(size_t)(r + 8) * N + col] = v2;
                C[(size_t)(r + 8) * N + col + 1] = v3;
            }
        }
    }
}

// ---------------- exact fp32 dt_raw ----------------
__global__ void dtraw_kernel(const float* __restrict__ x, const float* __restrict__ W_in,
                             const float* __restrict__ b_in)
{
    int row0 = blockIdx.x * 8;
    int tid = threadIdx.x;
    int r = tid >> 5, h = tid & 31;
    __shared__ float xs[8][DMODEL];
    for (int i = tid; i < 8 * DMODEL; i += 256)
        xs[i >> 10][i & 1023] = x[(size_t)(row0 + (i >> 10)) * DMODEL + (i & 1023)];
    __syncthreads();
    const float* wc = W_in + (DINPROJ - NHEADS) + h;
    float a0 = 0.f, a1 = 0.f, a2 = 0.f, a3 = 0.f;
#pragma unroll 2
    for (int k = 0; k < DMODEL; k += 4) {
        a0 = fmaf(xs[r][k + 0], wc[(size_t)(k + 0) * DINPROJ], a0);
        a1 = fmaf(xs[r][k + 1], wc[(size_t)(k + 1) * DINPROJ], a1);
        a2 = fmaf(xs[r][k + 2], wc[(size_t)(k + 2) * DINPROJ], a2);
        a3 = fmaf(xs[r][k + 3], wc[(size_t)(k + 3) * DINPROJ], a3);
    }
    g_draw[(size_t)(row0 + r) * NHEADS + h] =
        b_in[DINPROJ - NHEADS + h] + ((a0 + a1) + (a2 + a3));
}

// ---------------- conv + silu + fused xdt (4 seq positions / thread) --------
__global__ void conv_kernel(const float* __restrict__ conv_w, const float* __restrict__ conv_b)
{
    int idx = blockIdx.x * blockDim.x + threadIdx.x;
    if (idx >= (NROWS / 4) * CONVDIM) return;
    int ch = idx % CONVDIM;
    int rg = idx / CONVDIM;
    int row0 = rg * 4;
    int l0 = row0 % SEQ;
    float w0 = conv_w[ch * DCONV + 0], w1 = conv_w[ch * DCONV + 1];
    float w2 = conv_w[ch * DCONV + 2], w3 = conv_w[ch * DCONV + 3];
    float bv = conv_b[ch];
    float v[7];
#pragma unroll
    for (int j = 0; j < 7; j++) {
        int l = l0 + j - 3;
        v[j] = (l >= 0) ? g_zx[(size_t)(row0 + j - 3) * DINPROJ + DINNER + ch] : 0.f;
    }
#pragma unroll
    for (int i = 0; i < 4; i++) {
        float a = bv;
        a = fmaf(v[i], w0, a);
        a = fmaf(v[i + 1], w1, a);
        a = fmaf(v[i + 2], w2, a);
        a = fmaf(v[i + 3], w3, a);
        float o = siluf(a);
        size_t row = row0 + i;
        g_xbc[row * CONVDIM + ch] = o;
        if (ch < DINNER)
            g_xdt[row * DINNER + ch] = o * g_dt[row * NHEADS + (ch >> 6)];
    }
}

// ---------------- dt / dA + per-chunk inclusive cumsum (exact exp) ----------
__global__ void dtscan_kernel(const float* __restrict__ tdiff,
                              const float* __restrict__ A_log,
                              const float* __restrict__ dt_bias,
                              const float* __restrict__ time_decay)
{
    int blk = blockIdx.x;
    int c = blk % NC;
    int h = (blk / NC) % NHEADS;
    int b = blk / (NC * NHEADS);
    int l = threadIdx.x;
    __shared__ float s[CHUNKL];
    int row = b * SEQ + c * CHUNKL + l;
    float draw = g_draw[(size_t)row * NHEADS + h];
    float dt = softplusf(draw + dt_bias[h]);
    float Ah = -expf(A_log[h]);
    float spd = softplusf(time_decay[h]);
    float dA = dt * Ah - spd * tdiff[row];
    g_dt[(size_t)row * NHEADS + h] = dt;
    s[l] = dA;
    __syncthreads();
    for (int off = 1; off < CHUNKL; off <<= 1) {
        float v = (l >= off) ? s[l - off] : 0.f;
        __syncthreads();
        s[l] += v;
        __syncthreads();
    }
    g_acum[((size_t)(b * NHEADS + h)) * SEQ + c * CHUNKL + l] = s[l];
}

// ---------------- G = C @ B^T per (b,chunk)  [tf32 mma, 64x64 tiles] --------
__global__ __launch_bounds__(256)
void cbgemm_kernel()
{
    int bc = blockIdx.z;
    int l0 = blockIdx.y * 64, s0 = blockIdx.x * 64;
    __shared__ float As[16][72];
    __shared__ float Bs2[16][72];
    int tid = threadIdx.x;
    int lane = tid & 31, wid = tid >> 5;
    int wm = (wid & 3) * 16;
    int wn = (wid >> 2) * 32;
    int g = lane >> 2, tig = lane & 3;

    float acc[4][4];
#pragma unroll
    for (int j = 0; j < 4; j++)
#pragma unroll
        for (int v = 0; v < 4; v++) acc[j][v] = 0.f;

    const float* base = g_xbc + (size_t)bc * CHUNKL * CONVDIM;
    int r = tid >> 2, c4 = (tid & 3) << 2;
    for (int n0 = 0; n0 < DSTATE; n0 += 16) {
        float4 vc = *(const float4*)(base + (size_t)(l0 + r) * CONVDIM + DINNER + DSTATE + n0 + c4);
        As[c4 + 0][r] = tf32r(vc.x); As[c4 + 1][r] = tf32r(vc.y);
        As[c4 + 2][r] = tf32r(vc.z); As[c4 + 3][r] = tf32r(vc.w);
        float4 vb = *(const float4*)(base + (size_t)(s0 + r) * CONVDIM + DINNER + n0 + c4);
        Bs2[c4 + 0][r] = tf32r(vb.x); Bs2[c4 + 1][r] = tf32r(vb.y);
        Bs2[c4 + 2][r] = tf32r(vb.z); Bs2[c4 + 3][r] = tf32r(vb.w);
        __syncthreads();
#pragma unroll
        for (int ks = 0; ks < 2; ks++) {
            int kb = ks * 8;
            unsigned af[4], bf[4][2];
            af[0] = __float_as_uint(As[kb + tig][wm + g]);
            af[1] = __float_as_uint(As[kb + tig][wm + g + 8]);
            af[2] = __float_as_uint(As[kb + tig + 4][wm + g]);
            af[3] = __float_as_uint(As[kb + tig + 4][wm + g + 8]);
#pragma unroll
            for (int nt = 0; nt < 4; nt++) {
                int n = wn + nt * 8;
                bf[nt][0] = __float_as_uint(Bs2[kb + tig][n + g]);
                bf[nt][1] = __float_as_uint(Bs2[kb + tig + 4][n + g]);
            }
#pragma unroll
            for (int nt = 0; nt < 4; nt++)
                mma_tf32(acc[nt], af, bf[nt]);
        }
        __syncthreads();
    }
    float* Gp = g_G + (size_t)bc * CHUNKL * CHUNKL;
    int rr = l0 + wm + g;
#pragma unroll
    for (int nt = 0; nt < 4; nt++) {
        int col = s0 + wn + nt * 8 + 2 * tig;
        Gp[(size_t)rr * CHUNKL + col]     = acc[nt][0];
        Gp[(size_t)rr * CHUNKL + col + 1] = acc[nt][1];
        Gp[(size_t)(rr + 8) * CHUNKL + col]     = acc[nt][2];
        Gp[(size_t)(rr + 8) * CHUNKL + col + 1] = acc[nt][3];
    }
}

// ---------------- chunk states  [tf32 mma, __expf] ----------------
__global__ __launch_bounds__(256)
void states_kernel()
{
    int bch = blockIdx.x;
    int h = bch % NHEADS;
    int bc = bch / NHEADS;
    int b = bc / NC, c = bc % NC;
    int tid = threadIdx.x;
    int lane = tid & 31, wid = tid >> 5;
    int wm = (wid >> 1) * 16;
    int wn = (wid & 1) * 64;
    int g = lane >> 2, tig = lane & 3;

    __shared__ float w[CHUNKL];
    __shared__ float As[16][72];
    __shared__ float Bs[16][136];
    const float* ac = g_acum + ((size_t)(b * NHEADS + h)) * SEQ + c * CHUNKL;
    w[tid] = __expf(ac[CHUNKL - 1] - ac[tid]);
    __syncthreads();

    float acc[8][4];
#pragma unroll
    for (int j = 0; j < 8; j++)
#pragma unroll
        for (int v = 0; v < 4; v++) acc[j][v] = 0.f;

    for (int l0 = 0; l0 < CHUNKL; l0 += 16) {
        {
            int lr = tid >> 4, pc = (tid & 15) << 2;
            float4 v = *(const float4*)(g_xdt + ((size_t)(bc * CHUNKL + l0 + lr)) * DINNER + h * HEADDIM + pc);
            float ww = w[l0 + lr];
            As[lr][pc + 0] = tf32r(v.x * ww); As[lr][pc + 1] = tf32r(v.y * ww);
            As[lr][pc + 2] = tf32r(v.z * ww); As[lr][pc + 3] = tf32r(v.w * ww);
        }
#pragma unroll
        for (int u = 0; u < 2; u++) {
            int id = tid * 2 + u;
            int lr2 = id >> 5, nc4 = (id & 31) << 2;
            float4 vb = *(const float4*)(g_xbc + ((size_t)(bc * CHUNKL + l0 + lr2)) * CONVDIM + DINNER + nc4);
            Bs[lr2][nc4 + 0] = tf32r(vb.x); Bs[lr2][nc4 + 1] = tf32r(vb.y);
            Bs[lr2][nc4 + 2] = tf32r(vb.z); Bs[lr2][nc4 + 3] = tf32r(vb.w);
        }
        __syncthreads();
#pragma unroll
        for (int ks = 0; ks < 2; ks++) {
            int kb = ks * 8;
            unsigned af[4], bf[8][2];
            af[0] = __float_as_uint(As[kb + tig][wm + g]);
            af[1] = __float_as_uint(As[kb + tig][wm + g + 8]);
            af[2] = __float_as_uint(As[kb + tig + 4][wm + g]);
            af[3] = __float_as_uint(As[kb + tig + 4][wm + g + 8]);
#pragma unroll
            for (int nt = 0; nt < 8; nt++) {
                int n = wn + nt * 8;
                bf[nt][0] = __float_as_uint(Bs[kb + tig][n + g]);
                bf[nt][1] = __float_as_uint(Bs[kb + tig + 4][n + g]);
            }
#pragma unroll
            for (int nt = 0; nt < 8; nt++)
                mma_tf32(acc[nt], af, bf[nt]);
        }
        __syncthreads();
    }
    float* sp = g_states + (size_t)bch * HEADDIM * DSTATE;
    int r = wm + g;
#pragma unroll
    for (int nt = 0; nt < 8; nt++) {
        int col = wn + nt * 8 + 2 * tig;
        sp[(size_t)r * DSTATE + col]     = acc[nt][0];
        sp[(size_t)r * DSTATE + col + 1] = acc[nt][1];
        sp[(size_t)(r + 8) * DSTATE + col]     = acc[nt][2];
        sp[(size_t)(r + 8) * DSTATE + col + 1] = acc[nt][3];
    }
}

// ---------------- inter-chunk scan  [__expf] ----------------
__global__ void scan_kernel()
{
    int idx = blockIdx.x * blockDim.x + threadIdx.x;
    if (idx >= BB * NHEADS * HEADDIM * DSTATE) return;
    int n = idx & 127;
    int p = (idx >> 7) & 63;
    int h = (idx >> 13) & 31;
    int b = idx >> 18;
    float carry = 0.f;
    for (int c = 0; c < NC; c++) {
        size_t off = ((size_t)((b * NC + c) * NHEADS + h)) * (HEADDIM * DSTATE) + p * DSTATE + n;
        g_prev[off] = carry;
        float cd = __expf(g_acum[((size_t)(b * NHEADS + h)) * SEQ + c * CHUNKL + CHUNKL - 1]);
        carry = carry * cd + g_states[off];
    }
}

// ---------------- Y = (Y_diag + Y_off + D*xh) * silu(z)  [tf32 mma, __expf] -
__global__ __launch_bounds__(256)
void ydiag_kernel(const float* __restrict__ Dp)
{
    int bch = blockIdx.x;
    int h = bch % NHEADS;
    int bc = bch / NHEADS;
    int b = bc / NC;
    int tid = threadIdx.x;
    int lane = tid & 31, wid = tid >> 5;
    int g = lane >> 2, tig = lane & 3;
    int wm = wid * 32;

    __shared__ float Acs[CHUNKL];
    __shared__ float Gs[16][260];
    __shared__ float Xs[16][68];

    const float* ac = g_acum + ((size_t)(b * NHEADS + h)) * SEQ + (bc % NC) * CHUNKL;
    Acs[tid] = ac[tid];
    __syncthreads();
    float al = Acs[tid];
    float eal = __expf(al);

    float acc[2][8][4];
#pragma unroll
    for (int i = 0; i < 2; i++)
#pragma unroll
        for (int j = 0; j < 8; j++)
#pragma unroll
            for (int v = 0; v < 4; v++) acc[i][j][v] = 0.f;

    const float* Gp = g_G + (size_t)bc * CHUNKL * CHUNKL;

    for (int s0 = 0; s0 < CHUNKL; s0 += 16) {
        float4 gv[4];
#pragma unroll
        for (int q = 0; q < 4; q++)
            gv[q] = *(const float4*)(Gp + (size_t)tid * CHUNKL + s0 + q * 4);
        const float* gf = (const float*)gv;
#pragma unroll
        for (int i = 0; i < 16; i++) {
            int s = s0 + i;
            float v = 0.f;
            if (tid >= s) v = gf[i] * __expf(al - Acs[s]);
            Gs[i][tid] = tf32r(v);
        }
        {
            int lr = tid >> 4, pc = (tid & 15) << 2;
            float4 v4 = *(const float4*)(g_xdt + ((size_t)(bc * CHUNKL + s0 + lr)) * DINNER + h * HEADDIM + pc);
            Xs[lr][pc + 0] = tf32r(v4.x); Xs[lr][pc + 1] = tf32r(v4.y);
            Xs[lr][pc + 2] = tf32r(v4.z); Xs[lr][pc + 3] = tf32r(v4.w);
        }
        __syncthreads();
#pragma unroll
        for (int ks = 0; ks < 2; ks++) {
            int kb = ks * 8;
            unsigned af[2][4], bf[8][2];
#pragma unroll
            for (int mt = 0; mt < 2; mt++) {
                int m = wm + mt * 16;
                af[mt][0] = __float_as_uint(Gs[kb + tig][m + g]);
                af[mt][1] = __float_as_uint(Gs[kb + tig][m + g + 8]);
                af[mt][2] = __float_as_uint(Gs[kb + tig + 4][m + g]);
                af[mt][3] = __float_as_uint(Gs[kb + tig + 4][m + g + 8]);
            }
#pragma unroll
            for (int nt = 0; nt < 8; nt++) {
                int n = nt * 8;
                bf[nt][0] = __float_as_uint(Xs[kb + tig][n + g]);
                bf[nt][1] = __float_as_uint(Xs[kb + tig + 4][n + g]);
            }
#pragma unroll
            for (int mt = 0; mt < 2; mt++)
#pragma unroll
                for (int nt = 0; nt < 8; nt++)
                    mma_tf32(acc[mt][nt], af[mt], bf[nt]);
        }
        __syncthreads();
    }

    const float* pv_base = g_prev + (size_t)bch * HEADDIM * DSTATE;
    for (int n0 = 0; n0 < DSTATE; n0 += 16) {
        float4 cv[4];
#pragma unroll
        for (int q = 0; q < 4; q++)
            cv[q] = *(const float4*)(g_xbc + ((size_t)(bc * CHUNKL + tid)) * CONVDIM + DINNER + DSTATE + n0 + q * 4);
        const float* cf = (const float*)cv;
#pragma unroll
        for (int i = 0; i < 16; i++)
            Gs[i][tid] = tf32r(cf[i] * eal);
        {
            int p = tid >> 2, k4 = (tid & 3) << 2;
            float4 pvv = *(const float4*)(pv_base + (size_t)p * DSTATE + n0 + k4);
            Xs[k4 + 0][p] = tf32r(pvv.x); Xs[k4 + 1][p] = tf32r(pvv.y);
            Xs[k4 + 2][p] = tf32r(pvv.z); Xs[k4 + 3][p] = tf32r(pvv.w);
        }
        __syncthreads();
#pragma unroll
        for (int ks = 0; ks < 2; ks++) {
            int kb = ks * 8;
            unsigned af[2][4], bf[8][2];
#pragma unroll
            for (int mt = 0; mt < 2; mt++) {
                int m = wm + mt * 16;
                af[mt][0] = __float_as_uint(Gs[kb + tig][m + g]);
                af[mt][1] = __float_as_uint(Gs[kb + tig][m + g + 8]);
                af[mt][2] = __float_as_uint(Gs[kb + tig + 4][m + g]);
                af[mt][3] = __float_as_uint(Gs[kb + tig + 4][m + g + 8]);
            }
#pragma unroll
            for (int nt = 0; nt < 8; nt++) {
                int n = nt * 8;
                bf[nt][0] = __float_as_uint(Xs[kb + tig][n + g]);
                bf[nt][1] = __float_as_uint(Xs[kb + tig + 4][n + g]);
            }
#pragma unroll
            for (int mt = 0; mt < 2; mt++)
#pragma unroll
                for (int nt = 0; nt < 8; nt++)
                    mma_tf32(acc[mt][nt], af[mt], bf[nt]);
        }
        __syncthreads();
    }

    float Dh = Dp[h];
#pragma unroll
    for (int mt = 0; mt < 2; mt++) {
        int r0 = wm + mt * 16 + g;
#pragma unroll
        for (int nt = 0; nt < 8; nt++) {
            int pcol = nt * 8 + 2 * tig;
            int d = h * HEADDIM + pcol;
#pragma unroll
            for (int half = 0; half < 2; half++) {
                int l = r0 + half * 8;
                size_t row = (size_t)bc * CHUNKL + l;
                float xh0 = g_xbc[row * CONVDIM + d];
                float xh1 = g_xbc[row * CONVDIM + d + 1];
                float z0 = g_zx[row * DINPROJ + d];
                float z1 = g_zx[row * DINPROJ + d + 1];
                float v0 = acc[mt][nt][half * 2 + 0] + Dh * xh0;
                float v1 = acc[mt][nt][half * 2 + 1] + Dh * xh1;
                v0 *= siluf(z0);
                v1 *= siluf(z1);
                g_y[row * DINNER + d] = v0;
                g_y[row * DINNER + d + 1] = v1;
            }
        }
    }
}

// ---------------- gated RMS norm ----------------
__global__ void rms_kernel(const float* __restrict__ rms_w)
{
    int row = blockIdx.x;
    int tid = threadIdx.x;
    float* y = g_y + (size_t)row * DINNER;
    float ss = 0.f;
    for (int i = tid; i < DINNER; i += 256) { float v = y[i]; ss = fmaf(v, v, ss); }
    __shared__ float red[256];
    red[tid] = ss; __syncthreads();
    for (int o = 128; o > 0; o >>= 1) { if (tid < o) red[tid] += red[tid + o]; __syncthreads(); }
    float scale = rsqrtf(red[0] * (1.f / DINNER) + 1e-12f);
    for (int i = tid; i < DINNER; i += 256) y[i] = y[i] * scale * rms_w[i];
}

// ---------------- residual add + LayerNorm ----------------
__global__ void addln_kernel(const float* __restrict__ in1, const float* __restrict__ res,
                             const float* __restrict__ g, const float* __restrict__ bta,
                             float* __restrict__ out)
{
    int row = blockIdx.x;
    int tid = threadIdx.x;
    __shared__ float buf[DMODEL];
    __shared__ float red[256];
    float s = 0.f;
    for (int i = tid; i < DMODEL; i += 256) {
        float v = in1[(size_t)row * DMODEL + i] + res[(size_t)row * DMODEL + i];
        buf[i] = v; s += v;
    }
    red[tid] = s; __syncthreads();
    for (int o = 128; o > 0; o >>= 1) { if (tid < o) red[tid] += red[tid + o]; __syncthreads(); }
    float mu = red[0] * (1.f / DMODEL);
    __syncthreads();
    float vs = 0.f;
    for (int i = tid; i < DMODEL; i += 256) { float d = buf[i] - mu; vs = fmaf(d, d, vs); }
    red[tid] = vs; __syncthreads();
    for (int o = 128; o > 0; o >>= 1) { if (tid < o) red[tid] += red[tid + o]; __syncthreads(); }
    float inv = rsqrtf(red[0] * (1.f / DMODEL) + 1e-12f);
    for (int i = tid; i < DMODEL; i += 256)
        out[(size_t)row * DMODEL + i] = (buf[i] - mu) * inv * g[i] + bta[i];
}

// ---------------- launch ----------------
extern "C" void kernel_launch(void* const* d_in, const int* in_sizes, int n_in,
                              void* d_out, int out_size)
{
    const float* x          = (const float*)d_in[0];
    const float* time_diff  = (const float*)d_in[1];
    const float* W_in       = (const float*)d_in[2];
    const float* b_in       = (const float*)d_in[3];
    const float* conv_w     = (const float*)d_in[4];
    const float* conv_b     = (const float*)d_in[5];
    const float* A_log      = (const float*)d_in[6];
    const float* dt_bias    = (const float*)d_in[7];
    const float* Dp         = (const float*)d_in[8];
    const float* time_decay = (const float*)d_in[9];
    const float* rms_w      = (const float*)d_in[10];
    const float* W_out      = (const float*)d_in[11];
    const float* b_out      = (const float*)d_in[12];
    const float* ln_g       = (const float*)d_in[13];
    const float* ln_b       = (const float*)d_in[14];
    const float* fc1_w      = (const float*)d_in[15];
    const float* fc1_b      = (const float*)d_in[16];
    const float* fc2_w      = (const float*)d_in[17];
    const float* fc2_b      = (const float*)d_in[18];
    const float* ln2_g      = (const float*)d_in[19];
    const float* ln2_b      = (const float*)d_in[20];
    float* out = (float*)d_out;

    float *p_zx, *p_y, *p_hidden, *p_h, *p_ff, *p_ff2;
    cudaGetSymbolAddress((void**)&p_zx, g_zx);
    cudaGetSymbolAddress((void**)&p_y, g_y);
    cudaGetSymbolAddress((void**)&p_hidden, g_hidden);
    cudaGetSymbolAddress((void**)&p_h, g_h);
    cudaGetSymbolAddress((void**)&p_ff, g_ff);
    cudaGetSymbolAddress((void**)&p_ff2, g_ff2);

    cudaFuncSetAttribute(gemm_tc, cudaFuncAttributeMaxDynamicSharedMemorySize, GT_SMEM);

    // 1. in_proj
    gemm_tc<<<dim3((DINPROJ + 127) / 128, NROWS / 128), 256, GT_SMEM>>>(
        x, W_in, b_in, p_zx, NROWS, DINPROJ, DMODEL, 0);
    // 1b. exact fp32 dt_raw
    dtraw_kernel<<<NROWS / 8, 256>>>(x, W_in, b_in);
    // 2. dt / dA / chunk cumsum
    dtscan_kernel<<<BB * NHEADS * NC, CHUNKL>>>(time_diff, A_log, dt_bias, time_decay);
    // 3. conv + silu + fused xdt
    conv_kernel<<<((NROWS / 4) * CONVDIM + 255) / 256, 256>>>(conv_w, conv_b);
    // 4. G = C @ B^T  [tf32, 64x64]
    cbgemm_kernel<<<dim3(4, 4, BB * NC), 256>>>();
    // 5. chunk states [tf32, __expf]
    states_kernel<<<BB * NC * NHEADS, 256>>>();
    // 6. inter-chunk scan [__expf]
    scan_kernel<<<(BB * NHEADS * HEADDIM * DSTATE + 255) / 256, 256>>>();
    // 7. Y [tf32, __expf]
    ydiag_kernel<<<BB * NC * NHEADS, 256>>>(Dp);
    // 8. gated RMS norm
    rms_kernel<<<NROWS, 256>>>(rms_w);
    // 9. out_proj
    gemm_tc<<<dim3(DMODEL / 128, NROWS / 128), 256, GT_SMEM>>>(
        p_y, W_out, b_out, p_hidden, NROWS, DMODEL, DINNER, 0);
    // 10. h = LN(hidden + x)
    addln_kernel<<<NROWS, 256>>>(p_hidden, x, ln_g, ln_b, p_h);
    // 11. fc1 + hardswish
    gemm_tc<<<dim3(DFF / 128, NROWS / 128), 256, GT_SMEM>>>(
        p_h, fc1_w, fc1_b, p_ff, NROWS, DFF, DMODEL, 1);
    // 12. fc2
    gemm_tc<<<dim3(DMODEL / 128, NROWS / 128), 256, GT_SMEM>>>(
        p_ff, fc2_w, fc2_b, p_ff2, NROWS, DMODEL, DFF, 0);
    // 13. out = LN(ff2 + h)
    addln_kernel<<<NROWS, 256>>>(p_ff2, p_h, ln2_g, ln2_b, out);
    // 14. time_diff passthrough
    cudaMemcpyAsync(out + (size_t)NROWS * DMODEL, time_diff,
                    (size_t)BB * SEQ * sizeof(float), cudaMemcpyDeviceToDevice);
}